// round 15
// baseline (speedup 1.0000x reference)
#include <cuda_runtime.h>
#include <cstdint>

#define THREADS 128
#define BM 64
#define BN 64
#define DH 64
#define SQ 4096
#define SKV 4096
#define NT (SKV / BN)
#define BATCH 4

// smem: 4-stage ring of V tiles. buf k at k*16384: vh @ +0 (64 rows x 128B), vl @ +8192
// epilogue reuse: O exchange 16KB @0, lsum @65536
#define BUF_STRIDE 16384
#define VL_OFF 8192
#define LS_OFF 65536
#define SMEM_TOTAL 66048

// pre-split V in bf16x2 form (element pairs), 2MB each
__device__ uint32_t g_vh[(size_t)BATCH * SKV * DH / 2];
__device__ uint32_t g_vl[(size_t)BATCH * SKV * DH / 2];

extern __shared__ char smem_raw[];

__device__ __forceinline__ uint32_t su32(const void* p) {
    uint32_t a;
    asm("{ .reg .u64 t; cvta.to.shared.u64 t, %1; cvt.u32.u64 %0, t; }" : "=r"(a) : "l"(p));
    return a;
}
__device__ __forceinline__ uint32_t cvt2bf(float hi, float lo) {
    uint32_t r;
    asm("cvt.rn.bf16x2.f32 %0, %1, %2;" : "=r"(r) : "f"(hi), "f"(lo));
    return r;
}
// volatile variants: pinned in program order between volatile MMAs
__device__ __forceinline__ uint32_t cvt2bf_v(float hi, float lo) {
    uint32_t r;
    asm volatile("cvt.rn.bf16x2.f32 %0, %1, %2;" : "=r"(r) : "f"(hi), "f"(lo));
    return r;
}
__device__ __forceinline__ float exp_v(float x) {
    float r;
    float xs = x * 1.4426950408889634f;
    asm volatile("ex2.approx.ftz.f32 %0, %1;" : "=f"(r) : "f"(xs));
    return r;
}
__device__ __forceinline__ void ldsm4(uint32_t& r0, uint32_t& r1, uint32_t& r2, uint32_t& r3, uint32_t a) {
    asm volatile("ldmatrix.sync.aligned.m8n8.x4.shared.b16 {%0,%1,%2,%3}, [%4];"
                 : "=r"(r0), "=r"(r1), "=r"(r2), "=r"(r3) : "r"(a));
}
__device__ __forceinline__ void ldsm4t(uint32_t& r0, uint32_t& r1, uint32_t& r2, uint32_t& r3, uint32_t a) {
    asm volatile("ldmatrix.sync.aligned.m8n8.x4.trans.shared.b16 {%0,%1,%2,%3}, [%4];"
                 : "=r"(r0), "=r"(r1), "=r"(r2), "=r"(r3) : "r"(a));
}
__device__ __forceinline__ void mma16816(float* d, const uint32_t* a, uint32_t b0, uint32_t b1) {
    asm volatile("mma.sync.aligned.m16n8k16.row.col.f32.bf16.bf16.f32 "
                 "{%0,%1,%2,%3}, {%4,%5,%6,%7}, {%8,%9}, {%0,%1,%2,%3};"
                 : "+f"(d[0]), "+f"(d[1]), "+f"(d[2]), "+f"(d[3])
                 : "r"(a[0]), "r"(a[1]), "r"(a[2]), "r"(a[3]), "r"(b0), "r"(b1));
}
__device__ __forceinline__ void split4(float4 v, uint32_t& h01, uint32_t& h23, uint32_t& l01, uint32_t& l23) {
    h01 = cvt2bf(v.y, v.x);
    h23 = cvt2bf(v.w, v.z);
    float r0 = v.x - __uint_as_float(h01 << 16);
    float r1 = v.y - __uint_as_float(h01 & 0xFFFF0000u);
    float r2 = v.z - __uint_as_float(h23 << 16);
    float r3 = v.w - __uint_as_float(h23 & 0xFFFF0000u);
    l01 = cvt2bf(r1, r0);
    l23 = cvt2bf(r3, r2);
}
__device__ __forceinline__ void cpasync16(uint32_t dst, const uint32_t* src) {
    asm volatile("cp.async.cg.shared.global [%0], [%1], 16;" :: "r"(dst), "l"(src) : "memory");
}

// softmax for one 16x8 fragment: unnormalized exp -> bf16 packs.
// lsum accumulates the bf16-ROUNDED values so the dominant-key rounding error
// cancels between numerator (P.V) and denominator (l) at normalization.
__device__ __forceinline__ void softmax_frag(const float s[4], float& l01, float& l23,
                                             uint32_t& ph0, uint32_t& ph1)
{
    float e0 = exp_v(s[0]);
    float e1 = exp_v(s[1]);
    float e2 = exp_v(s[2]);
    float e3 = exp_v(s[3]);
    uint32_t h01 = cvt2bf_v(e1, e0);
    uint32_t h23 = cvt2bf_v(e3, e2);
    l01 += __uint_as_float(h01 << 16) + __uint_as_float(h01 & 0xFFFF0000u);
    l23 += __uint_as_float(h23 << 16) + __uint_as_float(h23 & 0xFFFF0000u);
    ph0 = h01;
    ph1 = h23;
}

// ---------------- pre-kernel: V -> (vh, vl) bf16 split ----------------
__global__ void __launch_bounds__(256)
vconv(const float* __restrict__ V)
{
    int i = blockIdx.x * 256 + threadIdx.x;
    float4 v = ((const float4*)V)[i];
    uint32_t h01, h23, l01, l23;
    split4(v, h01, h23, l01, l23);
    g_vh[2 * i] = h01; g_vh[2 * i + 1] = h23;
    g_vl[2 * i] = l01; g_vl[2 * i + 1] = l23;
}

// ---------------- main kernel: 128-thread CTAs, 2 CTAs/SM ----------------
__global__ void __launch_bounds__(THREADS, 2)
attn_hmma(const float* __restrict__ Q, float* __restrict__ O)
{
    const uint32_t sb = su32(smem_raw);
    const int tid = threadIdx.x;
    const int w = tid >> 5;        // 0..3
    const int lane = tid & 31;
    const int rg = w & 1;          // row group: 32 query rows
    const int kh = w >> 1;         // key half: 32 of 64 keys
    const int bq = blockIdx.x, b = blockIdx.y;

    const float* Qg = Q + ((size_t)b * SQ + (size_t)bq * BM) * DH;
    float* Og = O + ((size_t)b * SQ + (size_t)bq * BM) * DH;
    const size_t vbase = ((size_t)b * SKV) * (DH / 2);   // uint32 units

    // ---------------- stage Q -> A-fragments qh/ql [mf][kf][4] (uses buf0 region) ----------------
    uint32_t qh[2][4][4], ql[2][4][4];
    {
        uint2 lres[8];
        #pragma unroll
        for (int s = 0; s < 8; s++) {
            int idx = tid + THREADS * s;          // float4 idx over 64x16
            int row = idx >> 4, c4 = idx & 15;
            float4 v = *(const float4*)(Qg + row * DH + c4 * 4);
            uint32_t h01, h23, l01, l23;
            split4(v, h01, h23, l01, l23);
            *(uint2*)(smem_raw + row * 128 + ((c4 * 8) ^ ((row & 7) << 4))) = make_uint2(h01, h23);
            lres[s] = make_uint2(l01, l23);
        }
        __syncthreads();
        #pragma unroll
        for (int mf = 0; mf < 2; mf++) {
            int arow = rg * 32 + mf * 16 + (lane & 7) + ((lane >> 3) & 1) * 8;
            uint32_t abase = sb + arow * 128;
            uint32_t axor = (arow & 7) << 4;
            #pragma unroll
            for (int kf = 0; kf < 4; kf++) {
                uint32_t addr = abase + ((kf * 32 + (lane >> 4) * 16) ^ axor);
                ldsm4(qh[mf][kf][0], qh[mf][kf][1], qh[mf][kf][2], qh[mf][kf][3], addr);
            }
        }
        __syncthreads();
        #pragma unroll
        for (int s = 0; s < 8; s++) {
            int idx = tid + THREADS * s;
            int row = idx >> 4, c4 = idx & 15;
            *(uint2*)(smem_raw + row * 128 + ((c4 * 8) ^ ((row & 7) << 4))) = lres[s];
        }
        __syncthreads();
        #pragma unroll
        for (int mf = 0; mf < 2; mf++) {
            int arow = rg * 32 + mf * 16 + (lane & 7) + ((lane >> 3) & 1) * 8;
            uint32_t abase = sb + arow * 128;
            uint32_t axor = (arow & 7) << 4;
            #pragma unroll
            for (int kf = 0; kf < 4; kf++) {
                uint32_t addr = abase + ((kf * 32 + (lane >> 4) * 16) ^ axor);
                ldsm4(ql[mf][kf][0], ql[mf][kf][1], ql[mf][kf][2], ql[mf][kf][3], addr);
            }
        }
        __syncthreads();   // done reading buf0 region before cp.async overwrites it
    }

    // ---------------- persistent state ----------------
    float o[2][8][4];
    #pragma unroll
    for (int mf = 0; mf < 2; mf++)
        #pragma unroll
        for (int i = 0; i < 8; i++)
            #pragma unroll
            for (int j = 0; j < 4; j++) o[mf][i][j] = 0.0f;
    float lsum[2][2] = {{0.0f, 0.0f}, {0.0f, 0.0f}};
    uint32_t ph[2][2][4];                 // P fragments (bf16-rounded) for tile t-1

    // GEMM1 B addresses (buffer-relative): this warp's key half only
    const uint32_t lxor = (lane & 7) << 4;
    const uint32_t g1k = (uint32_t)(kh * 32 + (lane & 7)) * 128;
    const uint32_t g1a = sb + g1k + (((lane >> 3) * 16) ^ lxor);
    const uint32_t g1b = sb + g1k + ((64 + (lane >> 3) * 16) ^ lxor);
    // GEMM2 (trans): key-row base; in-row offset XORed per fragment
    const uint32_t g2rowbase = sb + (uint32_t)(kh * 32 + (lane & 7) + 8 * ((lane >> 3) & 1)) * 128;
    const uint32_t g2klo = (lane >> 4) * 16;

    // cp.async chunk coords (4 chunks per tensor per tile; 512 x 16B chunks per tensor)
    uint32_t dA[4], sA[4];
    #pragma unroll
    for (int s = 0; s < 4; s++) {
        int id = tid + THREADS * s;
        int rc = id >> 3, cc = id & 7;
        dA[s] = rc * 128 + ((cc * 16) ^ ((rc & 7) << 4));
        sA[s] = rc * 32 + cc * 4;
    }

    // prologue: issue tiles 0 and 1 into bufs 0 and 1 (two commit groups)
    #pragma unroll
    for (int pt = 0; pt < 2; pt++) {
        uint32_t nb = sb + pt * BUF_STRIDE;
        size_t g = vbase + (size_t)pt * BN * (DH / 2);
        #pragma unroll
        for (int s = 0; s < 4; s++) {
            cpasync16(nb + dA[s], g_vh + g + sA[s]);
            cpasync16(nb + VL_OFF + dA[s], g_vl + g + sA[s]);
        }
        asm volatile("cp.async.commit_group;" ::: "memory");
    }

    for (int t = 0; t < NT; t++) {
        if (t == NT - 1) { asm volatile("cp.async.wait_group 0;" ::: "memory"); }
        else             { asm volatile("cp.async.wait_group 1;" ::: "memory"); }
        __syncthreads();
        if (t + 2 < NT) {
            uint32_t nb = sb + ((t + 2) & 3) * BUF_STRIDE;
            size_t g = vbase + (size_t)(t + 2) * BN * (DH / 2);
            #pragma unroll
            for (int s = 0; s < 4; s++) {
                cpasync16(nb + dA[s], g_vh + g + sA[s]);
                cpasync16(nb + VL_OFF + dA[s], g_vl + g + sA[s]);
            }
            asm volatile("cp.async.commit_group;" ::: "memory");
        }
        const uint32_t bo1 = (uint32_t)(t & 3) * BUF_STRIDE;

        // ---- GEMM2(t-1): O += ph.vh + ph.vl (trans B, key half K=32, buf t-1) ----
        if (t > 0) {
            const uint32_t bo2 = (uint32_t)((t - 1) & 3) * BUF_STRIDE;
            #pragma unroll
            for (int kf = 0; kf < 2; kf++) {
                uint32_t kfo = bo2 + (uint32_t)kf * 2048;
                #pragma unroll
                for (int dh2 = 0; dh2 < 4; dh2++) {
                    uint32_t inrow = (uint32_t)((dh2 * 32 + g2klo) ^ lxor);
                    uint32_t hr0, hr1, hr2, hr3, lr0, lr1, lr2, lr3;
                    ldsm4t(hr0, hr1, hr2, hr3, g2rowbase + kfo + inrow);
                    ldsm4t(lr0, lr1, lr2, lr3, g2rowbase + kfo + VL_OFF + inrow);
                    // rotate over {acc even/odd} x {mf0, mf1}: consecutive MMAs independent
                    mma16816(o[0][2 * dh2],     ph[0][kf], hr0, hr1);
                    mma16816(o[1][2 * dh2],     ph[1][kf], hr0, hr1);
                    mma16816(o[0][2 * dh2 + 1], ph[0][kf], hr2, hr3);
                    mma16816(o[1][2 * dh2 + 1], ph[1][kf], hr2, hr3);
                    mma16816(o[0][2 * dh2],     ph[0][kf], lr0, lr1);
                    mma16816(o[1][2 * dh2],     ph[1][kf], lr0, lr1);
                    mma16816(o[0][2 * dh2 + 1], ph[0][kf], lr2, lr3);
                    mma16816(o[1][2 * dh2 + 1], ph[1][kf], lr2, lr3);
                }
            }
        }

        // ---- GEMM1(t) with softmax(t) chunks interleaved at nf granularity ----
        // schedule: nf0, nf1, sm(nf0), nf2, sm(nf1), nf3, sm(nf2), sm(nf3)  -> 6 steps
        float sfrag[2][4][4];
        #pragma unroll
        for (int mf = 0; mf < 2; mf++)
            #pragma unroll
            for (int i = 0; i < 4; i++)
                #pragma unroll
                for (int j = 0; j < 4; j++) sfrag[mf][i][j] = 0.0f;

        #pragma unroll
        for (int step = 0; step < 6; step++) {
            if (step < 4) {
                const int nf = step;
                uint32_t bh[4], bh2[4], bl[4], bl2[4];
                ldsm4(bh[0], bh[1], bh2[0], bh2[1], g1a + bo1 + nf * 1024);
                ldsm4(bh[2], bh[3], bh2[2], bh2[3], g1b + bo1 + nf * 1024);
                ldsm4(bl[0], bl[1], bl2[0], bl2[1], g1a + bo1 + VL_OFF + nf * 1024);
                ldsm4(bl[2], bl[3], bl2[2], bl2[3], g1b + bo1 + VL_OFF + nf * 1024);
                #pragma unroll
                for (int mf = 0; mf < 2; mf++) {
                    float* d = sfrag[mf][nf];
                    mma16816(d, qh[mf][0], bh[0], bh[1]);
                    mma16816(d, qh[mf][1], bh2[0], bh2[1]);
                    mma16816(d, qh[mf][2], bh[2], bh[3]);
                    mma16816(d, qh[mf][3], bh2[2], bh2[3]);
                    mma16816(d, qh[mf][0], bl[0], bl[1]);
                    mma16816(d, qh[mf][1], bl2[0], bl2[1]);
                    mma16816(d, qh[mf][2], bl[2], bl[3]);
                    mma16816(d, qh[mf][3], bl2[2], bl2[3]);
                    mma16816(d, ql[mf][0], bh[0], bh[1]);
                    mma16816(d, ql[mf][1], bh2[0], bh2[1]);
                    mma16816(d, ql[mf][2], bh[2], bh[3]);
                    mma16816(d, ql[mf][3], bh2[2], bh2[3]);
                }
            }
            // steps 2..5 handle softmax for nf = step-2 (tensor pipe stays fed by queued blocks)
            if (step >= 2) {
                const int nfs = step - 2;
                const int kf = nfs >> 1, hh = (nfs & 1) * 2;
                #pragma unroll
                for (int mf = 0; mf < 2; mf++) {
                    softmax_frag(sfrag[mf][nfs], lsum[mf][0], lsum[mf][1],
                                 ph[mf][kf][hh], ph[mf][kf][hh + 1]);
                }
            }
        }
    }

    // ---- drain: GEMM2(NT-1) ----
    {
        const uint32_t bo2 = (uint32_t)((NT - 1) & 3) * BUF_STRIDE;
        #pragma unroll
        for (int kf = 0; kf < 2; kf++) {
            uint32_t kfo = bo2 + (uint32_t)kf * 2048;
            #pragma unroll
            for (int dh2 = 0; dh2 < 4; dh2++) {
                uint32_t inrow = (uint32_t)((dh2 * 32 + g2klo) ^ lxor);
                uint32_t hr0, hr1, hr2, hr3, lr0, lr1, lr2, lr3;
                ldsm4t(hr0, hr1, hr2, hr3, g2rowbase + kfo + inrow);
                ldsm4t(lr0, lr1, lr2, lr3, g2rowbase + kfo + VL_OFF + inrow);
                mma16816(o[0][2 * dh2],     ph[0][kf], hr0, hr1);
                mma16816(o[1][2 * dh2],     ph[1][kf], hr0, hr1);
                mma16816(o[0][2 * dh2 + 1], ph[0][kf], hr2, hr3);
                mma16816(o[1][2 * dh2 + 1], ph[1][kf], hr2, hr3);
                mma16816(o[0][2 * dh2],     ph[0][kf], lr0, lr1);
                mma16816(o[1][2 * dh2],     ph[1][kf], lr0, lr1);
                mma16816(o[0][2 * dh2 + 1], ph[0][kf], lr2, lr3);
                mma16816(o[1][2 * dh2 + 1], ph[1][kf], lr2, lr3);
            }
        }
    }

    // ---------------- epilogue: combine the two key-half groups ----------------
    #pragma unroll
    for (int mf = 0; mf < 2; mf++)
        #pragma unroll
        for (int h = 0; h < 2; h++) {
            lsum[mf][h] += __shfl_xor_sync(0xffffffffu, lsum[mf][h], 1);
            lsum[mf][h] += __shfl_xor_sync(0xffffffffu, lsum[mf][h], 2);
        }

    __syncthreads();   // all tile compute done; reuse V smem for O exchange

    float* oex = (float*)smem_raw;             // [64][64] fp32 = 16KB (buf 0)
    float* ls  = (float*)(smem_raw + LS_OFF);  // [64] fp32

    if (kh == 0) {
        #pragma unroll
        for (int mf = 0; mf < 2; mf++) {
            int row0 = rg * 32 + mf * 16 + (lane >> 2);
            #pragma unroll
            for (int nf = 0; nf < 8; nf++) {
                int col = nf * 8 + (lane & 3) * 2;
                *(float2*)&oex[row0 * 64 + col] = make_float2(o[mf][nf][0], o[mf][nf][1]);
                *(float2*)&oex[(row0 + 8) * 64 + col] = make_float2(o[mf][nf][2], o[mf][nf][3]);
            }
            if ((lane & 3) == 0) {
                ls[row0] = lsum[mf][0];
                ls[row0 + 8] = lsum[mf][1];
            }
        }
    }
    __syncthreads();
    if (kh == 1) {
        #pragma unroll
        for (int mf = 0; mf < 2; mf++) {
            int row0 = rg * 32 + mf * 16 + (lane >> 2);
            float inv0 = 1.0f / (lsum[mf][0] + ls[row0]);
            float inv1 = 1.0f / (lsum[mf][1] + ls[row0 + 8]);
            #pragma unroll
            for (int nf = 0; nf < 8; nf++) {
                int col = nf * 8 + (lane & 3) * 2;
                float2 a = *(float2*)&oex[row0 * 64 + col];
                float2 c = *(float2*)&oex[(row0 + 8) * 64 + col];
                *(float2*)(Og + (size_t)row0 * DH + col) =
                    make_float2((o[mf][nf][0] + a.x) * inv0, (o[mf][nf][1] + a.y) * inv0);
                *(float2*)(Og + (size_t)(row0 + 8) * DH + col) =
                    make_float2((o[mf][nf][2] + c.x) * inv1, (o[mf][nf][3] + c.y) * inv1);
            }
        }
    }
}

extern "C" void kernel_launch(void* const* d_in, const int* in_sizes, int n_in,
                              void* d_out, int out_size)
{
    const float* Q = (const float*)d_in[0];   // query [4,4096,64] fp32
    const float* V = (const float*)d_in[1];   // value [4,4096,64] fp32
    float* O = (float*)d_out;                 // out   [4,4096,64] fp32

    // >48KB dynamic smem opt-in (persists across graph capture)
    (void)cudaFuncSetAttribute(attn_hmma,
                               cudaFuncAttributeMaxDynamicSharedMemorySize, SMEM_TOTAL);

    vconv<<<(BATCH * SKV * DH / 4) / 256, 256>>>(V);

    dim3 grid(SQ / BM, BATCH);
    attn_hmma<<<grid, THREADS, SMEM_TOTAL>>>(Q, O);
}

// round 16
// speedup vs baseline: 1.0701x; 1.0701x over previous
#include <cuda_runtime.h>
#include <cuda_fp16.h>
#include <cstdint>

#define THREADS 256
#define BM 128
#define BN 64
#define DH 64
#define SQ 4096
#define SKV 4096
#define NT (SKV / BN)
#define BATCH 4

// smem: 4-stage ring of V tiles (fp16). buf k at k*16384: vh @ +0 (64 rows x 128B), vl @ +8192
// epilogue reuse: O exchange 32KB @0, lsum @65536, rowmax @66048
#define BUF_STRIDE 16384
#define VL_OFF 8192
#define LS_OFF 65536
#define MS_OFF 66048
#define SMEM_TOTAL 66560

// pre-split V in fp16x2 form (element pairs), 2MB each
__device__ uint32_t g_vh[(size_t)BATCH * SKV * DH / 2];
__device__ uint32_t g_vl[(size_t)BATCH * SKV * DH / 2];

extern __shared__ char smem_raw[];

__device__ __forceinline__ uint32_t su32(const void* p) {
    uint32_t a;
    asm("{ .reg .u64 t; cvta.to.shared.u64 t, %1; cvt.u32.u64 %0, t; }" : "=r"(a) : "l"(p));
    return a;
}
// pack two f32 -> f16x2 (lo in low half)
__device__ __forceinline__ uint32_t cvt2h(float hi, float lo) {
    uint32_t r;
    asm("cvt.rn.f16x2.f32 %0, %1, %2;" : "=r"(r) : "f"(hi), "f"(lo));
    return r;
}
__device__ __forceinline__ float exp_v(float x) {
    float r;
    float xs = x * 1.4426950408889634f;
    asm volatile("ex2.approx.ftz.f32 %0, %1;" : "=f"(r) : "f"(xs));
    return r;
}
__device__ __forceinline__ void ldsm4(uint32_t& r0, uint32_t& r1, uint32_t& r2, uint32_t& r3, uint32_t a) {
    asm volatile("ldmatrix.sync.aligned.m8n8.x4.shared.b16 {%0,%1,%2,%3}, [%4];"
                 : "=r"(r0), "=r"(r1), "=r"(r2), "=r"(r3) : "r"(a));
}
__device__ __forceinline__ void ldsm4t(uint32_t& r0, uint32_t& r1, uint32_t& r2, uint32_t& r3, uint32_t a) {
    asm volatile("ldmatrix.sync.aligned.m8n8.x4.trans.shared.b16 {%0,%1,%2,%3}, [%4];"
                 : "=r"(r0), "=r"(r1), "=r"(r2), "=r"(r3) : "r"(a));
}
__device__ __forceinline__ void mma16816(float* d, const uint32_t* a, uint32_t b0, uint32_t b1) {
    asm volatile("mma.sync.aligned.m16n8k16.row.col.f32.f16.f16.f32 "
                 "{%0,%1,%2,%3}, {%4,%5,%6,%7}, {%8,%9}, {%0,%1,%2,%3};"
                 : "+f"(d[0]), "+f"(d[1]), "+f"(d[2]), "+f"(d[3])
                 : "r"(a[0]), "r"(a[1]), "r"(a[2]), "r"(a[3]), "r"(b0), "r"(b1));
}
// split float4 into fp16x2 high pair + residual-low pair
__device__ __forceinline__ void split4h(float4 v, uint32_t& h01, uint32_t& h23, uint32_t& l01, uint32_t& l23) {
    h01 = cvt2h(v.y, v.x);
    h23 = cvt2h(v.w, v.z);
    __half2 hp0 = *reinterpret_cast<__half2*>(&h01);
    __half2 hp1 = *reinterpret_cast<__half2*>(&h23);
    float r0 = v.x - __low2float(hp0);
    float r1 = v.y - __high2float(hp0);
    float r2 = v.z - __low2float(hp1);
    float r3 = v.w - __high2float(hp1);
    l01 = cvt2h(r1, r0);
    l23 = cvt2h(r3, r2);
}
__device__ __forceinline__ void cpasync16(uint32_t dst, const uint32_t* src) {
    asm volatile("cp.async.cg.shared.global [%0], [%1], 16;" :: "r"(dst), "l"(src) : "memory");
}

// ---------------- pre-kernel: V -> (vh, vl) fp16 split ----------------
__global__ void __launch_bounds__(256)
vconv(const float* __restrict__ V)
{
    int i = blockIdx.x * 256 + threadIdx.x;
    float4 v = ((const float4*)V)[i];
    uint32_t h01, h23, l01, l23;
    split4h(v, h01, h23, l01, l23);
    g_vh[2 * i] = h01; g_vh[2 * i + 1] = h23;
    g_vl[2 * i] = l01; g_vl[2 * i + 1] = l23;
}

// ---------------- main kernel ----------------
__global__ void __launch_bounds__(THREADS, 1)
attn_hmma(const float* __restrict__ Q, float* __restrict__ O)
{
    const uint32_t sb = su32(smem_raw);
    const int tid = threadIdx.x;
    const int w = tid >> 5;
    const int lane = tid & 31;
    const int rg = w & 3;          // row group: 32 query rows
    const int kh = w >> 2;         // key half: 32 of 64 keys
    const int bq = blockIdx.x, b = blockIdx.y;

    const float* Qg = Q + ((size_t)b * SQ + (size_t)bq * BM) * DH;
    float* Og = O + ((size_t)b * SQ + (size_t)bq * BM) * DH;
    const size_t vbase = ((size_t)b * SKV) * (DH / 2);   // uint32 units

    // ---------------- stage Q -> A-fragments qh/ql [mf][kf][4] (fp16, uses buf0 region) ----------------
    uint32_t qh[2][4][4], ql[2][4][4];
    {
        uint2 lres[8];
        #pragma unroll
        for (int s = 0; s < 8; s++) {
            int idx = tid + THREADS * s;          // float4 idx over 128x16
            int row = idx >> 4, c4 = idx & 15;
            float4 v = *(const float4*)(Qg + row * DH + c4 * 4);
            uint32_t h01, h23, l01, l23;
            split4h(v, h01, h23, l01, l23);
            *(uint2*)(smem_raw + row * 128 + ((c4 * 8) ^ ((row & 7) << 4))) = make_uint2(h01, h23);
            lres[s] = make_uint2(l01, l23);
        }
        __syncthreads();
        #pragma unroll
        for (int mf = 0; mf < 2; mf++) {
            int arow = rg * 32 + mf * 16 + (lane & 7) + ((lane >> 3) & 1) * 8;
            uint32_t abase = sb + arow * 128;
            uint32_t axor = (arow & 7) << 4;
            #pragma unroll
            for (int kf = 0; kf < 4; kf++) {
                uint32_t addr = abase + ((kf * 32 + (lane >> 4) * 16) ^ axor);
                ldsm4(qh[mf][kf][0], qh[mf][kf][1], qh[mf][kf][2], qh[mf][kf][3], addr);
            }
        }
        __syncthreads();
        #pragma unroll
        for (int s = 0; s < 8; s++) {
            int idx = tid + THREADS * s;
            int row = idx >> 4, c4 = idx & 15;
            *(uint2*)(smem_raw + row * 128 + ((c4 * 8) ^ ((row & 7) << 4))) = lres[s];
        }
        __syncthreads();
        #pragma unroll
        for (int mf = 0; mf < 2; mf++) {
            int arow = rg * 32 + mf * 16 + (lane & 7) + ((lane >> 3) & 1) * 8;
            uint32_t abase = sb + arow * 128;
            uint32_t axor = (arow & 7) << 4;
            #pragma unroll
            for (int kf = 0; kf < 4; kf++) {
                uint32_t addr = abase + ((kf * 32 + (lane >> 4) * 16) ^ axor);
                ldsm4(ql[mf][kf][0], ql[mf][kf][1], ql[mf][kf][2], ql[mf][kf][3], addr);
            }
        }
        __syncthreads();   // done reading buf0 region before cp.async overwrites it
    }

    // ---------------- persistent state ----------------
    float o[2][8][4];
    #pragma unroll
    for (int mf = 0; mf < 2; mf++)
        #pragma unroll
        for (int i = 0; i < 8; i++)
            #pragma unroll
            for (int j = 0; j < 4; j++) o[mf][i][j] = 0.0f;
    float lsum[2][2] = {{0.0f, 0.0f}, {0.0f, 0.0f}};
    float mrow[2][2] = {{-1e30f, -1e30f}, {-1e30f, -1e30f}};
    float sc[2][2]   = {{1.0f, 1.0f}, {1.0f, 1.0f}};   // O-rescale factor from previous softmax
    uint32_t ph[2][2][4];                 // P fragments (fp16, max-subtracted) for tile t-1

    // GEMM1 B addresses (buffer-relative): this warp's key half only
    const uint32_t lxor = (lane & 7) << 4;
    const uint32_t g1k = (uint32_t)(kh * 32 + (lane & 7)) * 128;
    const uint32_t g1a = sb + g1k + (((lane >> 3) * 16) ^ lxor);
    const uint32_t g1b = sb + g1k + ((64 + (lane >> 3) * 16) ^ lxor);
    // GEMM2 (trans): key-row base; in-row offset XORed per fragment
    const uint32_t g2rowbase = sb + (uint32_t)(kh * 32 + (lane & 7) + 8 * ((lane >> 3) & 1)) * 128;
    const uint32_t g2klo = (lane >> 4) * 16;

    // cp.async chunk coords (2 chunks per tensor per tile; 512 x 16B chunks per tensor)
    const int id0 = tid, id1 = tid + 256;
    const int r0c = id0 >> 3, c0c = id0 & 7;
    const int r1c = id1 >> 3, c1c = id1 & 7;
    const uint32_t d0 = r0c * 128 + ((c0c * 16) ^ ((r0c & 7) << 4));
    const uint32_t d1 = r1c * 128 + ((c1c * 16) ^ ((r1c & 7) << 4));
    const uint32_t s0 = r0c * 32 + c0c * 4;
    const uint32_t s1 = r1c * 32 + c1c * 4;

    // prologue: issue tiles 0 and 1 into bufs 0 and 1 (two commit groups)
    #pragma unroll
    for (int pt = 0; pt < 2; pt++) {
        uint32_t nb = sb + pt * BUF_STRIDE;
        size_t g = vbase + (size_t)pt * BN * (DH / 2);
        cpasync16(nb + d0, g_vh + g + s0);
        cpasync16(nb + VL_OFF + d0, g_vl + g + s0);
        cpasync16(nb + d1, g_vh + g + s1);
        cpasync16(nb + VL_OFF + d1, g_vl + g + s1);
        asm volatile("cp.async.commit_group;" ::: "memory");
    }

    for (int t = 0; t < NT; t++) {
        if (t == NT - 1) { asm volatile("cp.async.wait_group 0;" ::: "memory"); }
        else             { asm volatile("cp.async.wait_group 1;" ::: "memory"); }
        __syncthreads();
        if (t + 2 < NT) {
            uint32_t nb = sb + ((t + 2) & 3) * BUF_STRIDE;
            size_t g = vbase + (size_t)(t + 2) * BN * (DH / 2);
            cpasync16(nb + d0, g_vh + g + s0);
            cpasync16(nb + VL_OFF + d0, g_vl + g + s0);
            cpasync16(nb + d1, g_vh + g + s1);
            cpasync16(nb + VL_OFF + d1, g_vl + g + s1);
            asm volatile("cp.async.commit_group;" ::: "memory");
        }
        const uint32_t bo1 = (uint32_t)(t & 3) * BUF_STRIDE;

        // ---- GEMM2(t-1): O = O*sc + ph.vh (trans B, single product, buf t-1) ----
        if (t > 0) {
            #pragma unroll
            for (int mf = 0; mf < 2; mf++)
                #pragma unroll
                for (int nf = 0; nf < 8; nf++) {
                    o[mf][nf][0] *= sc[mf][0];
                    o[mf][nf][1] *= sc[mf][0];
                    o[mf][nf][2] *= sc[mf][1];
                    o[mf][nf][3] *= sc[mf][1];
                }
            const uint32_t bo2 = (uint32_t)((t - 1) & 3) * BUF_STRIDE;
            #pragma unroll
            for (int kf = 0; kf < 2; kf++) {
                uint32_t kfo = bo2 + (uint32_t)kf * 2048;
                #pragma unroll
                for (int dh2 = 0; dh2 < 4; dh2++) {
                    uint32_t inrow = (uint32_t)((dh2 * 32 + g2klo) ^ lxor);
                    uint32_t hr0, hr1, hr2, hr3;
                    ldsm4t(hr0, hr1, hr2, hr3, g2rowbase + kfo + inrow);
                    mma16816(o[0][2 * dh2],     ph[0][kf], hr0, hr1);
                    mma16816(o[1][2 * dh2],     ph[1][kf], hr0, hr1);
                    mma16816(o[0][2 * dh2 + 1], ph[0][kf], hr2, hr3);
                    mma16816(o[1][2 * dh2 + 1], ph[1][kf], hr2, hr3);
                }
            }
        }

        // ---- GEMM1(t): S[32 x 32] = qh.vh^T + qh.vl^T + ql.vh^T (fp16, buf t) ----
        float sfrag[2][4][4];
        #pragma unroll
        for (int mf = 0; mf < 2; mf++)
            #pragma unroll
            for (int i = 0; i < 4; i++)
                #pragma unroll
                for (int j = 0; j < 4; j++) sfrag[mf][i][j] = 0.0f;
        #pragma unroll
        for (int nf = 0; nf < 4; nf++) {
            uint32_t bh[4], bh2[4], bl[4], bl2[4];
            ldsm4(bh[0], bh[1], bh2[0], bh2[1], g1a + bo1 + nf * 1024);
            ldsm4(bh[2], bh[3], bh2[2], bh2[3], g1b + bo1 + nf * 1024);
            ldsm4(bl[0], bl[1], bl2[0], bl2[1], g1a + bo1 + VL_OFF + nf * 1024);
            ldsm4(bl[2], bl[3], bl2[2], bl2[3], g1b + bo1 + VL_OFF + nf * 1024);
            #pragma unroll
            for (int mf = 0; mf < 2; mf++) {
                float* d = sfrag[mf][nf];
                mma16816(d, qh[mf][0], bh[0], bh[1]);
                mma16816(d, qh[mf][1], bh2[0], bh2[1]);
                mma16816(d, qh[mf][2], bh[2], bh[3]);
                mma16816(d, qh[mf][3], bh2[2], bh2[3]);
                mma16816(d, qh[mf][0], bl[0], bl[1]);
                mma16816(d, qh[mf][1], bl2[0], bl2[1]);
                mma16816(d, qh[mf][2], bl[2], bl[3]);
                mma16816(d, qh[mf][3], bl2[2], bl2[3]);
                mma16816(d, ql[mf][0], bh[0], bh[1]);
                mma16816(d, ql[mf][1], bh2[0], bh2[1]);
                mma16816(d, ql[mf][2], bh[2], bh[3]);
                mma16816(d, ql[mf][3], bh2[2], bh2[3]);
            }
        }

        // ---- softmax(t): online max-subtracted exp -> fp16 P frags; lsum from ROUNDED values ----
        #pragma unroll
        for (int mf = 0; mf < 2; mf++) {
            float mx0 = -1e30f, mx1 = -1e30f;
            #pragma unroll
            for (int nf = 0; nf < 4; nf++) {
                mx0 = fmaxf(mx0, fmaxf(sfrag[mf][nf][0], sfrag[mf][nf][1]));
                mx1 = fmaxf(mx1, fmaxf(sfrag[mf][nf][2], sfrag[mf][nf][3]));
            }
            mx0 = fmaxf(mx0, __shfl_xor_sync(0xffffffffu, mx0, 1));
            mx0 = fmaxf(mx0, __shfl_xor_sync(0xffffffffu, mx0, 2));
            mx1 = fmaxf(mx1, __shfl_xor_sync(0xffffffffu, mx1, 1));
            mx1 = fmaxf(mx1, __shfl_xor_sync(0xffffffffu, mx1, 2));
            float mn0 = fmaxf(mrow[mf][0], mx0);
            float mn1 = fmaxf(mrow[mf][1], mx1);
            sc[mf][0] = exp_v(mrow[mf][0] - mn0);
            sc[mf][1] = exp_v(mrow[mf][1] - mn1);
            mrow[mf][0] = mn0;
            mrow[mf][1] = mn1;
            float l0 = lsum[mf][0] * sc[mf][0];
            float l1 = lsum[mf][1] * sc[mf][1];
            #pragma unroll
            for (int nf = 0; nf < 4; nf++) {
                float p0 = exp_v(sfrag[mf][nf][0] - mn0);
                float p1 = exp_v(sfrag[mf][nf][1] - mn0);
                float p2 = exp_v(sfrag[mf][nf][2] - mn1);
                float p3 = exp_v(sfrag[mf][nf][3] - mn1);
                uint32_t h01 = cvt2h(p1, p0);
                uint32_t h23 = cvt2h(p3, p2);
                __half2 hp0 = *reinterpret_cast<__half2*>(&h01);
                __half2 hp1 = *reinterpret_cast<__half2*>(&h23);
                l0 += __low2float(hp0) + __high2float(hp0);
                l1 += __low2float(hp1) + __high2float(hp1);
                int kf = nf >> 1, hh = (nf & 1) * 2;
                ph[mf][kf][hh] = h01;
                ph[mf][kf][hh + 1] = h23;
            }
            lsum[mf][0] = l0;
            lsum[mf][1] = l1;
        }
    }

    // ---- drain: rescale + GEMM2(NT-1) ----
    {
        #pragma unroll
        for (int mf = 0; mf < 2; mf++)
            #pragma unroll
            for (int nf = 0; nf < 8; nf++) {
                o[mf][nf][0] *= sc[mf][0];
                o[mf][nf][1] *= sc[mf][0];
                o[mf][nf][2] *= sc[mf][1];
                o[mf][nf][3] *= sc[mf][1];
            }
        const uint32_t bo2 = (uint32_t)((NT - 1) & 3) * BUF_STRIDE;
        #pragma unroll
        for (int kf = 0; kf < 2; kf++) {
            uint32_t kfo = bo2 + (uint32_t)kf * 2048;
            #pragma unroll
            for (int dh2 = 0; dh2 < 4; dh2++) {
                uint32_t inrow = (uint32_t)((dh2 * 32 + g2klo) ^ lxor);
                uint32_t hr0, hr1, hr2, hr3;
                ldsm4t(hr0, hr1, hr2, hr3, g2rowbase + kfo + inrow);
                mma16816(o[0][2 * dh2],     ph[0][kf], hr0, hr1);
                mma16816(o[1][2 * dh2],     ph[1][kf], hr0, hr1);
                mma16816(o[0][2 * dh2 + 1], ph[0][kf], hr2, hr3);
                mma16816(o[1][2 * dh2 + 1], ph[1][kf], hr2, hr3);
            }
        }
    }

    // ---------------- epilogue: combine the two key-half groups (max-aware) ----------------
    #pragma unroll
    for (int mf = 0; mf < 2; mf++)
        #pragma unroll
        for (int h = 0; h < 2; h++) {
            lsum[mf][h] += __shfl_xor_sync(0xffffffffu, lsum[mf][h], 1);
            lsum[mf][h] += __shfl_xor_sync(0xffffffffu, lsum[mf][h], 2);
        }

    __syncthreads();   // all tile compute done; reuse V smem for O exchange

    float* oex = (float*)smem_raw;             // [128][64] fp32 = 32KB (bufs 0-1)
    float* ls  = (float*)(smem_raw + LS_OFF);  // [128] fp32
    float* ms  = (float*)(smem_raw + MS_OFF);  // [128] fp32

    if (kh == 0) {
        #pragma unroll
        for (int mf = 0; mf < 2; mf++) {
            int row0 = rg * 32 + mf * 16 + (lane >> 2);
            #pragma unroll
            for (int nf = 0; nf < 8; nf++) {
                int col = nf * 8 + (lane & 3) * 2;
                *(float2*)&oex[row0 * 64 + col] = make_float2(o[mf][nf][0], o[mf][nf][1]);
                *(float2*)&oex[(row0 + 8) * 64 + col] = make_float2(o[mf][nf][2], o[mf][nf][3]);
            }
            if ((lane & 3) == 0) {
                ls[row0] = lsum[mf][0];
                ls[row0 + 8] = lsum[mf][1];
                ms[row0] = mrow[mf][0];
                ms[row0 + 8] = mrow[mf][1];
            }
        }
    }
    __syncthreads();
    if (kh == 1) {
        #pragma unroll
        for (int mf = 0; mf < 2; mf++) {
            int row0 = rg * 32 + mf * 16 + (lane >> 2);
            float ma0 = ms[row0], la0 = ls[row0];
            float ma1 = ms[row0 + 8], la1 = ls[row0 + 8];
            float M0 = fmaxf(mrow[mf][0], ma0);
            float M1 = fmaxf(mrow[mf][1], ma1);
            float fa0 = exp_v(ma0 - M0), fb0 = exp_v(mrow[mf][0] - M0);
            float fa1 = exp_v(ma1 - M1), fb1 = exp_v(mrow[mf][1] - M1);
            float inv0 = 1.0f / (la0 * fa0 + lsum[mf][0] * fb0);
            float inv1 = 1.0f / (la1 * fa1 + lsum[mf][1] * fb1);
            #pragma unroll
            for (int nf = 0; nf < 8; nf++) {
                int col = nf * 8 + (lane & 3) * 2;
                float2 a = *(float2*)&oex[row0 * 64 + col];
                float2 c = *(float2*)&oex[(row0 + 8) * 64 + col];
                *(float2*)(Og + (size_t)row0 * DH + col) =
                    make_float2((o[mf][nf][0] * fb0 + a.x * fa0) * inv0,
                                (o[mf][nf][1] * fb0 + a.y * fa0) * inv0);
                *(float2*)(Og + (size_t)(row0 + 8) * DH + col) =
                    make_float2((o[mf][nf][2] * fb1 + c.x * fa1) * inv1,
                                (o[mf][nf][3] * fb1 + c.y * fa1) * inv1);
            }
        }
    }
}

extern "C" void kernel_launch(void* const* d_in, const int* in_sizes, int n_in,
                              void* d_out, int out_size)
{
    const float* Q = (const float*)d_in[0];   // query [4,4096,64] fp32
    const float* V = (const float*)d_in[1];   // value [4,4096,64] fp32
    float* O = (float*)d_out;                 // out   [4,4096,64] fp32

    // >48KB dynamic smem opt-in (persists across graph capture)
    (void)cudaFuncSetAttribute(attn_hmma,
                               cudaFuncAttributeMaxDynamicSharedMemorySize, SMEM_TOTAL);

    vconv<<<(BATCH * SKV * DH / 4) / 256, 256>>>(V);

    dim3 grid(SQ / BM, BATCH);
    attn_hmma<<<grid, THREADS, SMEM_TOTAL>>>(Q, O);
}